// round 1
// baseline (speedup 1.0000x reference)
#include <cuda_runtime.h>
#include <math.h>

// ---------------- problem constants ----------------
#define BQ    2
#define TT    8
#define CDIM  192
#define NSP   576          // H*W = 24*24
#define TOK   9216         // B*T*N
#define DI    384          // d_inner
#define DS    16           // d_state
#define DTR   12
#define MLPH  768
#define NT_SEQ 1152        // B*N  (temporal sequences)

// ---------------- scratch (device globals; allocation-free) ----------------
__device__ float g_xn[TOK*CDIM];          // layernormed x, token order [bt, n, c]
__device__ float g_short[TOK*CDIM];       // shortcut
__device__ float g_xz[2][TOK*2*DI];       // in_proj out, per-mamba scan order
__device__ float g_u[2][TOK*DI];          // conv+silu output
__device__ float g_delta[2][TOK*DI];
__device__ float g_bc[2][TOK*2*DS];       // B then C per token
__device__ float g_y[2][TOK*DI];          // scan output (gated), token order
__device__ float g_x2[TOK*CDIM];          // after fusion residual
__device__ float g_h[TOK*CDIM];           // ln2 output
__device__ float g_hid[TOK*MLPH];         // mlp hidden
__device__ float g_W1[CDIM*DI];           // fusion_w[:, :192] @ s_out_proj_w
__device__ float g_W2[CDIM*DI];           // fusion_w[:, 192:] @ t_out_proj_w
__device__ float g_A[2][DI*DS];           // -exp(A_log)

// ---------------- prep: A = -exp(A_log); fold out_proj into fusion ----------------
__global__ void prep_kernel(const float* __restrict__ sAlog, const float* __restrict__ tAlog,
                            const float* __restrict__ fw,
                            const float* __restrict__ soutw, const float* __restrict__ toutw)
{
    int i = blockIdx.x * blockDim.x + threadIdx.x;
    if (i < 2*DI*DS) {
        int m = i / (DI*DS);
        int j = i % (DI*DS);
        g_A[m][j] = -expf(m ? tAlog[j] : sAlog[j]);
    }
    if (i < 2*CDIM*DI) {
        int m   = i / (CDIM*DI);
        int rem = i % (CDIM*DI);
        int c   = rem / DI;
        int j   = rem % DI;
        const float* ow = m ? toutw : soutw;
        float acc = 0.f;
        #pragma unroll 4
        for (int cp = 0; cp < CDIM; cp++)
            acc += fw[c*(2*CDIM) + m*CDIM + cp] * ow[cp*DI + j];
        if (m) g_W2[rem] = acc; else g_W1[rem] = acc;
    }
}

// ---------------- layernorm (warp per token) ----------------
// strided=1: src is x_in [BT, C, N]; else src is [tok, C] contiguous
__global__ void ln_kernel(const float* __restrict__ src, float* __restrict__ dstn,
                          float* __restrict__ dstcopy,
                          const float* __restrict__ w, const float* __restrict__ b,
                          int strided)
{
    int tok  = blockIdx.x * 4 + (threadIdx.x >> 5);
    int lane = threadIdx.x & 31;
    float v[6];
    if (strided) {
        int bt = tok / NSP, n = tok % NSP;
        const float* base = src + (size_t)bt * CDIM * NSP + n;
        #pragma unroll
        for (int j = 0; j < 6; j++) v[j] = base[(lane + 32*j) * NSP];
    } else {
        const float* base = src + (size_t)tok * CDIM;
        #pragma unroll
        for (int j = 0; j < 6; j++) v[j] = base[lane + 32*j];
    }
    float s = 0.f;
    #pragma unroll
    for (int j = 0; j < 6; j++) s += v[j];
    #pragma unroll
    for (int o = 16; o > 0; o >>= 1) s += __shfl_xor_sync(0xffffffffu, s, o);
    float mean = s * (1.f / CDIM);
    float q = 0.f;
    #pragma unroll
    for (int j = 0; j < 6; j++) { float d = v[j] - mean; q += d * d; }
    #pragma unroll
    for (int o = 16; o > 0; o >>= 1) q += __shfl_xor_sync(0xffffffffu, q, o);
    float rstd = rsqrtf(q * (1.f / CDIM) + 1e-5f);
    #pragma unroll
    for (int j = 0; j < 6; j++) {
        int c = lane + 32*j;
        float out = (v[j] - mean) * rstd * w[c] + b[c];
        dstn[(size_t)tok * CDIM + c] = out;
        if (dstcopy) dstcopy[(size_t)tok * CDIM + c] = v[j];
    }
}

// ---------------- generic fp32 GEMM: C[M,N] = act(A[M,K] @ B[N,K]^T + bias + addend) ----
// flags bit0: gelu epilogue; bit1: gather A rows through temporal scan-order map
__global__ __launch_bounds__(256) void gemm_kernel(
    const float* __restrict__ A, const float* __restrict__ B, float* __restrict__ C,
    const float* __restrict__ bias, const float* __restrict__ addend,
    int M, int N, int K, int flags)
{
    __shared__ float As[16][64];
    __shared__ float Bs[16][64];
    __shared__ int   rs[64];
    int tid = threadIdx.x;
    int m0 = blockIdx.y * 64, n0 = blockIdx.x * 64;

    if (tid < 64) {
        int r = m0 + tid;
        if (flags & 2) { // scan-order row r = (b*N+n)*T + t  ->  token (b*T+t)*N + n
            int bb = r / (NSP*TT);
            int rem = r - bb * (NSP*TT);
            int nn = rem >> 3;
            int t  = rem & 7;
            r = (bb * TT + t) * NSP + nn;
        }
        rs[tid] = r;
    }
    __syncthreads();

    int arow = tid >> 2, ak = (tid & 3) * 4;   // 64 rows x 16 k
    int ty = tid >> 4, tx = tid & 15;
    int srcrow = rs[arow];

    float acc[4][4];
    #pragma unroll
    for (int i = 0; i < 4; i++)
        #pragma unroll
        for (int j = 0; j < 4; j++) acc[i][j] = 0.f;

    for (int kt = 0; kt < K; kt += 16) {
        float4 av = *reinterpret_cast<const float4*>(&A[(size_t)srcrow * K + kt + ak]);
        float4 bv = *reinterpret_cast<const float4*>(&B[(size_t)(n0 + arow) * K + kt + ak]);
        __syncthreads();
        As[ak+0][arow] = av.x; As[ak+1][arow] = av.y; As[ak+2][arow] = av.z; As[ak+3][arow] = av.w;
        Bs[ak+0][arow] = bv.x; Bs[ak+1][arow] = bv.y; Bs[ak+2][arow] = bv.z; Bs[ak+3][arow] = bv.w;
        __syncthreads();
        #pragma unroll
        for (int kk = 0; kk < 16; kk++) {
            float4 a4 = *reinterpret_cast<const float4*>(&As[kk][ty*4]);
            float4 b4 = *reinterpret_cast<const float4*>(&Bs[kk][tx*4]);
            float aa[4] = {a4.x, a4.y, a4.z, a4.w};
            float bb[4] = {b4.x, b4.y, b4.z, b4.w};
            #pragma unroll
            for (int i = 0; i < 4; i++)
                #pragma unroll
                for (int j = 0; j < 4; j++) acc[i][j] += aa[i] * bb[j];
        }
    }

    float4 bb4 = make_float4(0.f,0.f,0.f,0.f);
    if (bias) bb4 = *reinterpret_cast<const float4*>(&bias[n0 + tx*4]);
    #pragma unroll
    for (int i = 0; i < 4; i++) {
        int mm = m0 + ty*4 + i;
        size_t off = (size_t)mm * N + n0 + tx*4;
        float v[4] = {acc[i][0] + bb4.x, acc[i][1] + bb4.y, acc[i][2] + bb4.z, acc[i][3] + bb4.w};
        if (addend) {
            float4 ad = *reinterpret_cast<const float4*>(&addend[off]);
            v[0] += ad.x; v[1] += ad.y; v[2] += ad.z; v[3] += ad.w;
        }
        if (flags & 1) {
            #pragma unroll
            for (int j = 0; j < 4; j++)
                v[j] = 0.5f * v[j] * (1.f + erff(v[j] * 0.70710678118654752f));
        }
        float4 res = make_float4(v[0], v[1], v[2], v[3]);
        *reinterpret_cast<float4*>(&C[off]) = res;
    }
}

// ---------------- conv(4, depthwise)+silu, x_proj, dt_proj, softplus (block per token) ----
__global__ void xproj_kernel(int m, int L,
                             const float* __restrict__ convw, const float* __restrict__ convb,
                             const float* __restrict__ xpw,
                             const float* __restrict__ dpw, const float* __restrict__ dpb)
{
    int r = blockIdx.x;
    int pos = r % L;
    const float* xz = g_xz[m];
    __shared__ float su[DI];
    __shared__ float sdbc[DTR + 2*DS];
    int tid = threadIdx.x;

    for (int d = tid; d < DI; d += 128) {
        float acc = convb[d];
        #pragma unroll
        for (int k = 0; k < 4; k++) {
            int pp = pos - 3 + k;
            if (pp >= 0) acc += convw[d*4 + k] * xz[(size_t)(r - 3 + k) * (2*DI) + d];
        }
        float uu = acc / (1.f + __expf(-acc));   // silu
        su[d] = uu;
        g_u[m][(size_t)r * DI + d] = uu;
    }
    __syncthreads();

    if (tid < DTR + 2*DS) {
        const float* wrow = &xpw[tid * DI];
        float acc = 0.f;
        #pragma unroll 4
        for (int k = 0; k < DI; k++) acc += su[k] * wrow[k];
        sdbc[tid] = acc;
    }
    __syncthreads();

    if (tid < 2*DS) g_bc[m][(size_t)r * (2*DS) + tid] = sdbc[DTR + tid];

    for (int d = tid; d < DI; d += 128) {
        float acc = dpb[d];
        #pragma unroll
        for (int rr = 0; rr < DTR; rr++) acc += sdbc[rr] * dpw[d*DTR + rr];
        g_delta[m][(size_t)r * DI + d] = (acc > 15.f) ? acc : log1pf(__expf(acc));
    }
}

// ---------------- selective scan: warp = (seq, 2 d's); lane = state n ----------------
__global__ void scan_kernel(int m, int nseq, int L, int temporal, const float* __restrict__ Dp)
{
    int gw   = (blockIdx.x * blockDim.x + threadIdx.x) >> 5;
    int lane = threadIdx.x & 31;
    int seq  = gw / (DI/2);
    int dp   = gw % (DI/2);
    if (seq >= nseq) return;
    int sub = lane >> 4, n = lane & 15;
    int d = dp * 2 + sub;

    float a  = g_A[m][d*DS + n];
    float Dd = Dp[d];
    const float* delta = g_delta[m];
    const float* u     = g_u[m];
    const float* bc    = g_bc[m];
    const float* xz    = g_xz[m];
    float* y           = g_y[m];

    int b_ = 0, nsp = 0;
    if (temporal) { b_ = seq / NSP; nsp = seq % NSP; }
    int base = seq * L;

    float h = 0.f;
    for (int pos = 0; pos < L; ++pos) {
        int r = base + pos;
        float dl = __ldg(&delta[(size_t)r*DI + d]);
        float uu = __ldg(&u[(size_t)r*DI + d]);
        float Bv = __ldg(&bc[(size_t)r*(2*DS) + n]);
        float Cv = __ldg(&bc[(size_t)r*(2*DS) + DS + n]);
        float dA = __expf(dl * a);
        h = h * dA + dl * uu * Bv;
        float part = h * Cv;
        part += __shfl_xor_sync(0xffffffffu, part, 1);
        part += __shfl_xor_sync(0xffffffffu, part, 2);
        part += __shfl_xor_sync(0xffffffffu, part, 4);
        part += __shfl_xor_sync(0xffffffffu, part, 8);
        if (n == 0) {
            float z  = xz[(size_t)r*(2*DI) + DI + d];
            float yv = part + uu * Dd;
            float g  = z / (1.f + __expf(-z));   // silu(z)
            int tok = temporal ? ((b_ * TT + pos) * NSP + nsp) : r;
            y[(size_t)tok * DI + d] = yv * g;
        }
    }
}

// ---------------- final transpose [bt, n, c] -> [bt, c, n] ----------------
__global__ void out_transpose(float* __restrict__ out)
{
    int o = blockIdx.x * 256 + threadIdx.x;
    if (o >= TOK * CDIM) return;
    int n    = o % NSP;
    int rest = o / NSP;
    int c    = rest % CDIM;
    int bt   = rest / CDIM;
    out[o] = g_xn[(size_t)(bt * NSP + n) * CDIM + c];
}

// ---------------- host launcher ----------------
extern "C" void kernel_launch(void* const* d_in, const int* in_sizes, int n_in,
                              void* d_out, int out_size)
{
    const float* x_in   = (const float*)d_in[0];
    const float* n1w    = (const float*)d_in[1];
    const float* n1b    = (const float*)d_in[2];
    const float* s_inw  = (const float*)d_in[3];
    const float* s_cw   = (const float*)d_in[4];
    const float* s_cb   = (const float*)d_in[5];
    const float* s_xpw  = (const float*)d_in[6];
    const float* s_dpw  = (const float*)d_in[7];
    const float* s_dpb  = (const float*)d_in[8];
    const float* s_Alog = (const float*)d_in[9];
    const float* s_D    = (const float*)d_in[10];
    const float* s_outw = (const float*)d_in[11];
    const float* t_inw  = (const float*)d_in[12];
    const float* t_cw   = (const float*)d_in[13];
    const float* t_cb   = (const float*)d_in[14];
    const float* t_xpw  = (const float*)d_in[15];
    const float* t_dpw  = (const float*)d_in[16];
    const float* t_dpb  = (const float*)d_in[17];
    const float* t_Alog = (const float*)d_in[18];
    const float* t_D    = (const float*)d_in[19];
    const float* t_outw = (const float*)d_in[20];
    const float* fw     = (const float*)d_in[21];
    const float* fb     = (const float*)d_in[22];
    const float* n2w    = (const float*)d_in[23];
    const float* n2b    = (const float*)d_in[24];
    const float* w1     = (const float*)d_in[25];
    const float* b1     = (const float*)d_in[26];
    const float* w2     = (const float*)d_in[27];
    const float* b2     = (const float*)d_in[28];
    float* out = (float*)d_out;

    float *p_xn, *p_short, *p_xz, *p_y, *p_x2, *p_h, *p_hid, *p_W1, *p_W2;
    cudaGetSymbolAddress((void**)&p_xn,   g_xn);
    cudaGetSymbolAddress((void**)&p_short,g_short);
    cudaGetSymbolAddress((void**)&p_xz,   g_xz);
    cudaGetSymbolAddress((void**)&p_y,    g_y);
    cudaGetSymbolAddress((void**)&p_x2,   g_x2);
    cudaGetSymbolAddress((void**)&p_h,    g_h);
    cudaGetSymbolAddress((void**)&p_hid,  g_hid);
    cudaGetSymbolAddress((void**)&p_W1,   g_W1);
    cudaGetSymbolAddress((void**)&p_W2,   g_W2);
    float* p_xz0 = p_xz;
    float* p_xz1 = p_xz + (size_t)TOK * 2 * DI;
    float* p_y0  = p_y;
    float* p_y1  = p_y + (size_t)TOK * DI;

    // 0. precompute A and folded fusion weights
    prep_kernel<<<576, 256>>>(s_Alog, t_Alog, fw, s_outw, t_outw);

    // 1. transpose + LN1 (also keep shortcut)
    ln_kernel<<<TOK/4, 128>>>(x_in, p_xn, p_short, n1w, n1b, 1);

    // 2. in_proj GEMMs (spatial: token order == scan order; temporal: gathered rows)
    gemm_kernel<<<dim3(768/64, TOK/64), 256>>>(p_xn, s_inw, p_xz0, nullptr, nullptr, TOK, 2*DI, CDIM, 0);
    gemm_kernel<<<dim3(768/64, TOK/64), 256>>>(p_xn, t_inw, p_xz1, nullptr, nullptr, TOK, 2*DI, CDIM, 2);

    // 3. conv+silu + x_proj + dt_proj + softplus
    xproj_kernel<<<TOK, 128>>>(0, NSP, s_cw, s_cb, s_xpw, s_dpw, s_dpb);
    xproj_kernel<<<TOK, 128>>>(1, TT,  t_cw, t_cb, t_xpw, t_dpw, t_dpb);

    // 4. selective scans (outputs gated by silu(z), written in token order)
    scan_kernel<<<(16     * (DI/2)) / 4, 128>>>(0, 16,     NSP, 0, s_D);
    scan_kernel<<<(NT_SEQ * (DI/2)) / 4, 128>>>(1, NT_SEQ, TT,  1, t_D);

    // 5. fused out_proj + fusion + residual:  x2 = short + fb + y_s@W1^T + y_t@W2^T
    gemm_kernel<<<dim3(CDIM/64, TOK/64), 256>>>(p_y0, p_W1, p_x2, fb, p_short, TOK, CDIM, DI, 0);
    gemm_kernel<<<dim3(CDIM/64, TOK/64), 256>>>(p_y1, p_W2, p_x2, nullptr, p_x2, TOK, CDIM, DI, 0);

    // 6. LN2 + MLP + residual
    ln_kernel<<<TOK/4, 128>>>(p_x2, p_h, nullptr, n2w, n2b, 0);
    gemm_kernel<<<dim3(MLPH/64, TOK/64), 256>>>(p_h,   w1, p_hid, b1, nullptr, TOK, MLPH, CDIM, 1);
    gemm_kernel<<<dim3(CDIM/64, TOK/64), 256>>>(p_hid, w2, p_xn,  b2, p_x2,    TOK, CDIM, MLPH, 0);

    // 7. output transpose [bt,n,c] -> [b,t,c,h,w]
    out_transpose<<<(TOK*CDIM + 255)/256, 256>>>(out);
}

// round 2
// speedup vs baseline: 2.0761x; 2.0761x over previous
#include <cuda_runtime.h>
#include <math.h>

// ---------------- problem constants ----------------
#define BQ    2
#define TT    8
#define CDIM  192
#define NSP   576          // H*W
#define TOK   9216         // B*T*N
#define DI    384          // d_inner
#define DS    16           // d_state
#define DTR   12
#define MLPH  768
#define NT_SEQ 1152        // B*N (temporal sequences)

// ---------------- scratch (device globals; allocation-free) ----------------
__device__ float g_xn[TOK*CDIM];          // layernormed x / final pre-transpose result
__device__ float g_short[TOK*CDIM];       // shortcut
__device__ float g_xz[2][TOK*2*DI];       // in_proj out, per-mamba scan order
__device__ float g_u[2][TOK*DI];          // conv+silu output
__device__ float g_delta[2][TOK*DI];
__device__ float g_bc[2][TOK*2*DS];       // B then C per scan row
__device__ float g_y[TOK*2*DI];           // merged scan outputs (token order): cols 0-383 spatial, 384-767 temporal
__device__ float g_x2[TOK*CDIM];          // after fusion residual
__device__ float g_h[TOK*CDIM];           // ln2 output
__device__ float g_hid[TOK*MLPH];         // mlp hidden
__device__ float g_W12[CDIM*2*DI];        // [192 x 768] folded fusion @ out_proj (concat)
__device__ float g_A[2][DI*DS];           // -exp(A_log)
__device__ float g_cwT[2][4*DI];          // conv weights transposed [k][d]
__device__ float g_xpwT[2][DI*(DTR+2*DS)];// x_proj transposed [k][o], o<44
__device__ float g_dpwT[2][DTR*DI];       // dt_proj transposed [rr][d]

// ---------------- prep: transposed weights, A, folded fusion ----------------
__global__ void prep_kernel(const float* __restrict__ sAlog, const float* __restrict__ tAlog,
                            const float* __restrict__ fw,
                            const float* __restrict__ soutw, const float* __restrict__ toutw,
                            const float* __restrict__ scw, const float* __restrict__ tcw,
                            const float* __restrict__ sxpw, const float* __restrict__ txpw,
                            const float* __restrict__ sdpw, const float* __restrict__ tdpw)
{
    int i = blockIdx.x * blockDim.x + threadIdx.x;
    if (i < 2*DI*DS) {
        int m = i / (DI*DS), j = i % (DI*DS);
        g_A[m][j] = -expf(m ? tAlog[j] : sAlog[j]);
    }
    if (i < 2*4*DI) {
        int m = i / (4*DI), rem = i % (4*DI);
        int k = rem / DI, d = rem % DI;
        g_cwT[m][k*DI + d] = (m ? tcw : scw)[d*4 + k];
    }
    if (i < 2*DI*(DTR+2*DS)) {
        int m = i / (DI*(DTR+2*DS)), rem = i % (DI*(DTR+2*DS));
        int k = rem / (DTR+2*DS), o = rem % (DTR+2*DS);
        g_xpwT[m][k*(DTR+2*DS) + o] = (m ? txpw : sxpw)[o*DI + k];
    }
    if (i < 2*DTR*DI) {
        int m = i / (DTR*DI), rem = i % (DTR*DI);
        int rr = rem / DI, d = rem % DI;
        g_dpwT[m][rr*DI + d] = (m ? tdpw : sdpw)[d*DTR + rr];
    }
    if (i < CDIM*2*DI) {
        int c = i / (2*DI), q = i % (2*DI);
        int m = q / DI, j = q % DI;
        const float* ow = m ? toutw : soutw;
        const float* fr = fw + c*(2*CDIM) + m*CDIM;
        float acc = 0.f;
        #pragma unroll 4
        for (int cp = 0; cp < CDIM; cp++)
            acc = fmaf(fr[cp], ow[cp*DI + j], acc);
        g_W12[i] = acc;
    }
}

// ---------------- LN1 with tiled transpose (src is [BT, C, N]) ----------------
__global__ __launch_bounds__(256) void ln1_kernel(const float* __restrict__ src,
                                                  const float* __restrict__ w, const float* __restrict__ b)
{
    __shared__ float s[CDIM][33];
    int bt = blockIdx.x;
    int n0 = blockIdx.y * 32;
    int tid = threadIdx.x;
    // coalesced load: 192 rows (c) x 32 cols (n)
    #pragma unroll
    for (int i = 0; i < 24; i++) {
        int idx = tid + 256*i;
        int c = idx >> 5, nl = idx & 31;
        s[c][nl] = src[((size_t)bt*CDIM + c)*NSP + n0 + nl];
    }
    __syncthreads();
    int warp = tid >> 5, lane = tid & 31;
    for (int jj = 0; jj < 4; jj++) {
        int tt = warp + 8*jj;
        float v[6];
        #pragma unroll
        for (int j = 0; j < 6; j++) v[j] = s[lane + 32*j][tt];
        float sum = 0.f;
        #pragma unroll
        for (int j = 0; j < 6; j++) sum += v[j];
        #pragma unroll
        for (int o = 16; o > 0; o >>= 1) sum += __shfl_xor_sync(0xffffffffu, sum, o);
        float mean = sum * (1.f/CDIM);
        float q = 0.f;
        #pragma unroll
        for (int j = 0; j < 6; j++) { float d = v[j]-mean; q += d*d; }
        #pragma unroll
        for (int o = 16; o > 0; o >>= 1) q += __shfl_xor_sync(0xffffffffu, q, o);
        float rstd = rsqrtf(q * (1.f/CDIM) + 1e-5f);
        size_t tok = (size_t)bt*NSP + n0 + tt;
        #pragma unroll
        for (int j = 0; j < 6; j++) {
            int c = lane + 32*j;
            g_xn[tok*CDIM + c] = (v[j]-mean)*rstd*w[c] + b[c];
            g_short[tok*CDIM + c] = v[j];
        }
    }
}

// ---------------- LN2 (contiguous, warp per token) ----------------
__global__ void ln2_kernel(const float* __restrict__ src, float* __restrict__ dst,
                           const float* __restrict__ w, const float* __restrict__ b)
{
    int tok  = blockIdx.x * 4 + (threadIdx.x >> 5);
    int lane = threadIdx.x & 31;
    const float* base = src + (size_t)tok * CDIM;
    float v[6];
    #pragma unroll
    for (int j = 0; j < 6; j++) v[j] = base[lane + 32*j];
    float s = 0.f;
    #pragma unroll
    for (int j = 0; j < 6; j++) s += v[j];
    #pragma unroll
    for (int o = 16; o > 0; o >>= 1) s += __shfl_xor_sync(0xffffffffu, s, o);
    float mean = s * (1.f / CDIM);
    float q = 0.f;
    #pragma unroll
    for (int j = 0; j < 6; j++) { float d = v[j] - mean; q += d * d; }
    #pragma unroll
    for (int o = 16; o > 0; o >>= 1) q += __shfl_xor_sync(0xffffffffu, q, o);
    float rstd = rsqrtf(q * (1.f / CDIM) + 1e-5f);
    #pragma unroll
    for (int j = 0; j < 6; j++) {
        int c = lane + 32*j;
        dst[(size_t)tok * CDIM + c] = (v[j] - mean) * rstd * w[c] + b[c];
    }
}

// ---------------- GEMM: C[M,N] = act(A[M,K] @ B[N,K]^T + bias + addend) ----------------
// 128x64 tile, 8x4 microtile, 256 threads. flags bit0: gelu; bit1: temporal row gather on A.
__global__ __launch_bounds__(256) void gemm_kernel(
    const float* __restrict__ A, const float* __restrict__ B, float* __restrict__ C,
    const float* __restrict__ bias, const float* __restrict__ addend,
    int M, int N, int K, int flags)
{
    __shared__ float As[16][132];
    __shared__ float Bs[16][68];
    __shared__ int   rs[128];
    int tid = threadIdx.x;
    int m0 = blockIdx.y * 128, n0 = blockIdx.x * 64;

    if (tid < 128) {
        int r = m0 + tid;
        if (flags & 2) { // scan-order row -> token row
            int bb = r / (NSP*TT);
            int rem = r - bb * (NSP*TT);
            int nn = rem >> 3;
            int t  = rem & 7;
            r = (bb * TT + t) * NSP + nn;
        }
        rs[tid] = r;
    }
    __syncthreads();

    int rowA = tid >> 2;           // 0..63
    int kA   = (tid & 3) * 4;
    const float* Arow0 = A + (size_t)rs[rowA]      * K + kA;
    const float* Arow1 = A + (size_t)rs[rowA + 64] * K + kA;
    const float* Brow  = B + (size_t)(n0 + rowA)   * K + kA;

    int ty = tid >> 4, tx = tid & 15;
    float acc[8][4];
    #pragma unroll
    for (int i = 0; i < 8; i++)
        #pragma unroll
        for (int j = 0; j < 4; j++) acc[i][j] = 0.f;

    for (int kt = 0; kt < K; kt += 16) {
        float4 a0 = *reinterpret_cast<const float4*>(Arow0 + kt);
        float4 a1 = *reinterpret_cast<const float4*>(Arow1 + kt);
        float4 b0 = *reinterpret_cast<const float4*>(Brow  + kt);
        __syncthreads();
        As[kA+0][rowA] = a0.x; As[kA+1][rowA] = a0.y; As[kA+2][rowA] = a0.z; As[kA+3][rowA] = a0.w;
        As[kA+0][rowA+64] = a1.x; As[kA+1][rowA+64] = a1.y; As[kA+2][rowA+64] = a1.z; As[kA+3][rowA+64] = a1.w;
        Bs[kA+0][rowA] = b0.x; Bs[kA+1][rowA] = b0.y; Bs[kA+2][rowA] = b0.z; Bs[kA+3][rowA] = b0.w;
        __syncthreads();
        #pragma unroll
        for (int kk = 0; kk < 16; kk++) {
            float4 av0 = *reinterpret_cast<const float4*>(&As[kk][ty*8]);
            float4 av1 = *reinterpret_cast<const float4*>(&As[kk][ty*8+4]);
            float4 bv  = *reinterpret_cast<const float4*>(&Bs[kk][tx*4]);
            float aa[8] = {av0.x,av0.y,av0.z,av0.w,av1.x,av1.y,av1.z,av1.w};
            float bb[4] = {bv.x,bv.y,bv.z,bv.w};
            #pragma unroll
            for (int i = 0; i < 8; i++)
                #pragma unroll
                for (int j = 0; j < 4; j++) acc[i][j] = fmaf(aa[i], bb[j], acc[i][j]);
        }
    }

    float4 bb4 = make_float4(0.f,0.f,0.f,0.f);
    if (bias) bb4 = *reinterpret_cast<const float4*>(&bias[n0 + tx*4]);
    #pragma unroll
    for (int i = 0; i < 8; i++) {
        int mm = m0 + ty*8 + i;
        size_t off = (size_t)mm * N + n0 + tx*4;
        float v[4] = {acc[i][0] + bb4.x, acc[i][1] + bb4.y, acc[i][2] + bb4.z, acc[i][3] + bb4.w};
        if (addend) {
            float4 ad = *reinterpret_cast<const float4*>(&addend[off]);
            v[0] += ad.x; v[1] += ad.y; v[2] += ad.z; v[3] += ad.w;
        }
        if (flags & 1) {
            #pragma unroll
            for (int j = 0; j < 4; j++)
                v[j] = 0.5f * v[j] * (1.f + erff(v[j] * 0.70710678118654752f));
        }
        *reinterpret_cast<float4*>(&C[off]) = make_float4(v[0], v[1], v[2], v[3]);
    }
}

// ---------------- conv+silu, x_proj, dt_proj, softplus (block per scan row) ----------------
__global__ void xproj_kernel(int m, int L, const float* __restrict__ cb, const float* __restrict__ dpb)
{
    int r = blockIdx.x;
    int pos = r % L;
    const float* xz   = g_xz[m];
    const float* cwT  = g_cwT[m];
    const float* xpwT = g_xpwT[m];
    const float* dpwT = g_dpwT[m];
    __shared__ float su[DI];
    __shared__ float sdbc[DTR + 2*DS];
    int tid = threadIdx.x;

    #pragma unroll
    for (int i = 0; i < 3; i++) {
        int d = tid + 128*i;
        float acc = cb[d];
        #pragma unroll
        for (int k = 0; k < 4; k++) {
            int pp = pos - 3 + k;
            if (pp >= 0) acc = fmaf(cwT[k*DI + d], xz[(size_t)(r - 3 + k) * (2*DI) + d], acc);
        }
        float uu = acc / (1.f + __expf(-acc));
        su[d] = uu;
        g_u[m][(size_t)r * DI + d] = uu;
    }
    __syncthreads();

    if (tid < DTR + 2*DS) {
        float acc = 0.f;
        #pragma unroll 8
        for (int k = 0; k < DI; k++) acc = fmaf(su[k], xpwT[k*(DTR+2*DS) + tid], acc);
        sdbc[tid] = acc;
    }
    __syncthreads();

    if (tid < 2*DS) g_bc[m][(size_t)r * (2*DS) + tid] = sdbc[DTR + tid];

    #pragma unroll
    for (int i = 0; i < 3; i++) {
        int d = tid + 128*i;
        float acc = dpb[d];
        #pragma unroll
        for (int rr = 0; rr < DTR; rr++) acc = fmaf(sdbc[rr], dpwT[rr*DI + d], acc);
        g_delta[m][(size_t)r * DI + d] = (acc > 15.f) ? acc : log1pf(__expf(acc));
    }
}

// ---------------- selective scan: warp = (seq, 2 d's); lane = (sub, state n) ------------
// unrolled x4 with deferred, interleaved shuffle reductions
__global__ void scan_kernel(int m, int nseq, int L, int temporal, const float* __restrict__ Dp)
{
    int gw   = (blockIdx.x * blockDim.x + threadIdx.x) >> 5;
    int lane = threadIdx.x & 31;
    int seq  = gw / (DI/2);
    int dp   = gw % (DI/2);
    if (seq >= nseq) return;
    int sub = lane >> 4, n = lane & 15;
    int d = dp * 2 + sub;

    float a  = g_A[m][d*DS + n];
    float Dd = Dp[d];
    const float* delta = g_delta[m];
    const float* u     = g_u[m];
    const float* bc    = g_bc[m];
    const float* xz    = g_xz[m];
    int ycol = m * DI + d;

    int b_ = 0, nsp = 0;
    if (temporal) { b_ = seq / NSP; nsp = seq % NSP; }
    int base = seq * L;

    float h = 0.f;
    for (int pos = 0; pos < L; pos += 4) {
        float dl[4], uu[4], Bv[4], Cv[4];
        #pragma unroll
        for (int j = 0; j < 4; j++) {
            size_t r = base + pos + j;
            dl[j] = __ldg(&delta[r*DI + d]);
            uu[j] = __ldg(&u[r*DI + d]);
            Bv[j] = __ldg(&bc[r*(2*DS) + n]);
            Cv[j] = __ldg(&bc[r*(2*DS) + DS + n]);
        }
        float dA[4], dBu[4];
        #pragma unroll
        for (int j = 0; j < 4; j++) {
            dA[j]  = __expf(dl[j] * a);
            dBu[j] = dl[j] * uu[j] * Bv[j];
        }
        float part[4];
        #pragma unroll
        for (int j = 0; j < 4; j++) {
            h = fmaf(h, dA[j], dBu[j]);
            part[j] = h * Cv[j];
        }
        #pragma unroll
        for (int off = 1; off <= 8; off <<= 1)
            #pragma unroll
            for (int j = 0; j < 4; j++)
                part[j] += __shfl_xor_sync(0xffffffffu, part[j], off);
        if (n == 0) {
            #pragma unroll
            for (int j = 0; j < 4; j++) {
                size_t r = base + pos + j;
                float z  = xz[r*(2*DI) + DI + d];
                float g  = z / (1.f + __expf(-z));
                int tok = temporal ? ((b_ * TT + pos + j) * NSP + nsp) : (int)r;
                g_y[(size_t)tok * (2*DI) + ycol] = (part[j] + uu[j] * Dd) * g;
            }
        }
    }
}

// ---------------- final tiled transpose [bt, n, c] -> [bt, c, n] ----------------
__global__ __launch_bounds__(256) void out_transpose(float* __restrict__ out)
{
    __shared__ float s[32][193];
    int bt = blockIdx.x;
    int n0 = blockIdx.y * 32;
    int tid = threadIdx.x;
    #pragma unroll
    for (int i = 0; i < 24; i++) {
        int idx = tid + 256*i;
        int nl = idx / CDIM, c = idx % CDIM;
        s[nl][c] = g_xn[((size_t)bt*NSP + n0 + nl)*CDIM + c];
    }
    __syncthreads();
    #pragma unroll
    for (int i = 0; i < 24; i++) {
        int idx = tid + 256*i;
        int c = idx >> 5, nl = idx & 31;
        out[((size_t)bt*CDIM + c)*NSP + n0 + nl] = s[nl][c];
    }
}

// ---------------- host launcher ----------------
extern "C" void kernel_launch(void* const* d_in, const int* in_sizes, int n_in,
                              void* d_out, int out_size)
{
    const float* x_in   = (const float*)d_in[0];
    const float* n1w    = (const float*)d_in[1];
    const float* n1b    = (const float*)d_in[2];
    const float* s_inw  = (const float*)d_in[3];
    const float* s_cw   = (const float*)d_in[4];
    const float* s_cb   = (const float*)d_in[5];
    const float* s_xpw  = (const float*)d_in[6];
    const float* s_dpw  = (const float*)d_in[7];
    const float* s_dpb  = (const float*)d_in[8];
    const float* s_Alog = (const float*)d_in[9];
    const float* s_D    = (const float*)d_in[10];
    const float* s_outw = (const float*)d_in[11];
    const float* t_inw  = (const float*)d_in[12];
    const float* t_cw   = (const float*)d_in[13];
    const float* t_cb   = (const float*)d_in[14];
    const float* t_xpw  = (const float*)d_in[15];
    const float* t_dpw  = (const float*)d_in[16];
    const float* t_dpb  = (const float*)d_in[17];
    const float* t_Alog = (const float*)d_in[18];
    const float* t_D    = (const float*)d_in[19];
    const float* t_outw = (const float*)d_in[20];
    const float* fw     = (const float*)d_in[21];
    const float* fb     = (const float*)d_in[22];
    const float* n2w    = (const float*)d_in[23];
    const float* n2b    = (const float*)d_in[24];
    const float* w1     = (const float*)d_in[25];
    const float* b1     = (const float*)d_in[26];
    const float* w2     = (const float*)d_in[27];
    const float* b2     = (const float*)d_in[28];
    float* out = (float*)d_out;

    float *p_xn, *p_short, *p_xz, *p_y, *p_x2, *p_h, *p_hid, *p_W12;
    cudaGetSymbolAddress((void**)&p_xn,   g_xn);
    cudaGetSymbolAddress((void**)&p_short,g_short);
    cudaGetSymbolAddress((void**)&p_xz,   g_xz);
    cudaGetSymbolAddress((void**)&p_y,    g_y);
    cudaGetSymbolAddress((void**)&p_x2,   g_x2);
    cudaGetSymbolAddress((void**)&p_h,    g_h);
    cudaGetSymbolAddress((void**)&p_hid,  g_hid);
    cudaGetSymbolAddress((void**)&p_W12,  g_W12);
    float* p_xz0 = p_xz;
    float* p_xz1 = p_xz + (size_t)TOK * 2 * DI;

    // 0. transposed weights + A + folded fusion
    prep_kernel<<<576, 256>>>(s_Alog, t_Alog, fw, s_outw, t_outw,
                              s_cw, t_cw, s_xpw, t_xpw, s_dpw, t_dpw);

    // 1. transpose + LN1 (keeps shortcut)
    ln1_kernel<<<dim3(16, 18), 256>>>(x_in, n1w, n1b);

    // 2. in_proj GEMMs
    gemm_kernel<<<dim3(768/64, TOK/128), 256>>>(p_xn, s_inw, p_xz0, nullptr, nullptr, TOK, 2*DI, CDIM, 0);
    gemm_kernel<<<dim3(768/64, TOK/128), 256>>>(p_xn, t_inw, p_xz1, nullptr, nullptr, TOK, 2*DI, CDIM, 2);

    // 3. conv+silu + x_proj + dt_proj + softplus (all weight loads coalesced)
    xproj_kernel<<<TOK, 128>>>(0, NSP, s_cb, s_dpb);
    xproj_kernel<<<TOK, 128>>>(1, TT,  t_cb, t_dpb);

    // 4. selective scans (gated outputs into merged y buffer, token order)
    scan_kernel<<<(16     * (DI/2)) / 4, 128>>>(0, 16,     NSP, 0, s_D);
    scan_kernel<<<(NT_SEQ * (DI/2)) / 4, 128>>>(1, NT_SEQ, TT,  1, t_D);

    // 5. merged out_proj + fusion + residual: x2 = short + fb + y @ W12^T  (K=768)
    gemm_kernel<<<dim3(CDIM/64, TOK/128), 256>>>(p_y, p_W12, p_x2, fb, p_short, TOK, CDIM, 2*DI, 0);

    // 6. LN2 + MLP + residual
    ln2_kernel<<<TOK/4, 128>>>(p_x2, p_h, n2w, n2b);
    gemm_kernel<<<dim3(MLPH/64, TOK/128), 256>>>(p_h,   w1, p_hid, b1, nullptr, TOK, MLPH, CDIM, 1);
    gemm_kernel<<<dim3(CDIM/64, TOK/128), 256>>>(p_hid, w2, p_xn,  b2, p_x2,    TOK, CDIM, MLPH, 0);

    // 7. output tiled transpose [bt,n,c] -> [b,t,c,h,w]
    out_transpose<<<dim3(16, 18), 256>>>(out);
}

// round 3
// speedup vs baseline: 2.2691x; 1.0929x over previous
#include <cuda_runtime.h>
#include <math.h>

// ---------------- problem constants ----------------
#define BQ    2
#define TT    8
#define CDIM  192
#define NSP   576          // H*W
#define TOK   9216         // B*T*N
#define DI    384          // d_inner
#define DS    16           // d_state
#define DTR   12
#define MLPH  768
#define XZW   1536         // merged in_proj width (s:768 | t:768)

// ---------------- scratch (device globals; allocation-free) ----------------
__device__ float g_xn[TOK*CDIM];          // layernormed x / final pre-transpose result
__device__ float g_short[TOK*CDIM];       // shortcut (token order)
__device__ float g_xz[TOK*XZW];           // merged in_proj out, token order
__device__ float g_u[2][TOK*DI];          // conv+silu output (token order)
__device__ float g_delta[2][TOK*DI];
__device__ float g_bc[2][TOK*2*DS];       // B then C per token
__device__ float g_y[TOK*2*DI];           // merged gated scan outputs (token order)
__device__ float g_x2[TOK*CDIM];          // after fusion residual
__device__ float g_h[TOK*CDIM];           // ln2 output
__device__ float g_hid[TOK*MLPH];         // mlp hidden
__device__ float g_Win[XZW*CDIM];         // concat [s_in_proj; t_in_proj]
__device__ float g_W12[CDIM*2*DI];        // folded fusion @ out_proj (concat)
__device__ float g_A[2][DI*DS];           // -exp(A_log)
__device__ float g_cwT[2][4*DI];          // conv weights transposed [k][d]
__device__ float g_dpwT[2][DTR*DI];       // dt_proj transposed [rr][d]

// ---------------- prep ----------------
__global__ void prep_kernel(const float* __restrict__ sAlog, const float* __restrict__ tAlog,
                            const float* __restrict__ fw,
                            const float* __restrict__ soutw, const float* __restrict__ toutw,
                            const float* __restrict__ scw, const float* __restrict__ tcw,
                            const float* __restrict__ sdpw, const float* __restrict__ tdpw,
                            const float* __restrict__ sinw, const float* __restrict__ tinw)
{
    int i = blockIdx.x * blockDim.x + threadIdx.x;
    if (i < 2*DI*DS) {
        int m = i / (DI*DS), j = i % (DI*DS);
        g_A[m][j] = -expf(m ? tAlog[j] : sAlog[j]);
    }
    if (i < 2*4*DI) {
        int m = i / (4*DI), rem = i % (4*DI);
        int k = rem / DI, d = rem % DI;
        g_cwT[m][k*DI + d] = (m ? tcw : scw)[d*4 + k];
    }
    if (i < 2*DTR*DI) {
        int m = i / (DTR*DI), rem = i % (DTR*DI);
        int rr = rem / DI, d = rem % DI;
        g_dpwT[m][rr*DI + d] = (m ? tdpw : sdpw)[d*DTR + rr];
    }
    if (i < XZW*CDIM) {   // concat in_proj weights
        int row = i / CDIM;
        g_Win[i] = (row < 768) ? sinw[i] : tinw[i - 768*CDIM];
    }
    if (i < CDIM*2*DI) {  // fold out_proj into fusion
        int c = i / (2*DI), q = i % (2*DI);
        int m = q / DI, j = q % DI;
        const float* ow = m ? toutw : soutw;
        const float* fr = fw + c*(2*CDIM) + m*CDIM;
        float acc = 0.f;
        #pragma unroll 4
        for (int cp = 0; cp < CDIM; cp++)
            acc = fmaf(fr[cp], ow[cp*DI + j], acc);
        g_W12[i] = acc;
    }
}

// ---------------- LN1 with tiled transpose (src is [BT, C, N]) ----------------
__global__ __launch_bounds__(256) void ln1_kernel(const float* __restrict__ src,
                                                  const float* __restrict__ w, const float* __restrict__ b)
{
    __shared__ float s[CDIM][33];
    int bt = blockIdx.x;
    int n0 = blockIdx.y * 32;
    int tid = threadIdx.x;
    #pragma unroll
    for (int i = 0; i < 24; i++) {
        int idx = tid + 256*i;
        int c = idx >> 5, nl = idx & 31;
        s[c][nl] = src[((size_t)bt*CDIM + c)*NSP + n0 + nl];
    }
    __syncthreads();
    int warp = tid >> 5, lane = tid & 31;
    for (int jj = 0; jj < 4; jj++) {
        int tt = warp + 8*jj;
        float v[6];
        #pragma unroll
        for (int j = 0; j < 6; j++) v[j] = s[lane + 32*j][tt];
        float sum = 0.f;
        #pragma unroll
        for (int j = 0; j < 6; j++) sum += v[j];
        #pragma unroll
        for (int o = 16; o > 0; o >>= 1) sum += __shfl_xor_sync(0xffffffffu, sum, o);
        float mean = sum * (1.f/CDIM);
        float q = 0.f;
        #pragma unroll
        for (int j = 0; j < 6; j++) { float d = v[j]-mean; q += d*d; }
        #pragma unroll
        for (int o = 16; o > 0; o >>= 1) q += __shfl_xor_sync(0xffffffffu, q, o);
        float rstd = rsqrtf(q * (1.f/CDIM) + 1e-5f);
        size_t tok = (size_t)bt*NSP + n0 + tt;
        #pragma unroll
        for (int j = 0; j < 6; j++) {
            int c = lane + 32*j;
            g_xn[tok*CDIM + c] = (v[j]-mean)*rstd*w[c] + b[c];
            g_short[tok*CDIM + c] = v[j];
        }
    }
}

// ---------------- LN2 (contiguous, warp per token) ----------------
__global__ void ln2_kernel(const float* __restrict__ src, float* __restrict__ dst,
                           const float* __restrict__ w, const float* __restrict__ b)
{
    int tok  = blockIdx.x * 4 + (threadIdx.x >> 5);
    int lane = threadIdx.x & 31;
    const float* base = src + (size_t)tok * CDIM;
    float v[6];
    #pragma unroll
    for (int j = 0; j < 6; j++) v[j] = base[lane + 32*j];
    float s = 0.f;
    #pragma unroll
    for (int j = 0; j < 6; j++) s += v[j];
    #pragma unroll
    for (int o = 16; o > 0; o >>= 1) s += __shfl_xor_sync(0xffffffffu, s, o);
    float mean = s * (1.f / CDIM);
    float q = 0.f;
    #pragma unroll
    for (int j = 0; j < 6; j++) { float d = v[j] - mean; q += d * d; }
    #pragma unroll
    for (int o = 16; o > 0; o >>= 1) q += __shfl_xor_sync(0xffffffffu, q, o);
    float rstd = rsqrtf(q * (1.f / CDIM) + 1e-5f);
    #pragma unroll
    for (int j = 0; j < 6; j++) {
        int c = lane + 32*j;
        dst[(size_t)tok * CDIM + c] = (v[j] - mean) * rstd * w[c] + b[c];
    }
}

// ---------------- pipelined GEMM: C[M,N] = act(A @ B^T + bias + addend) ----------------
// 128x64 tile, Ktile=16, 8x4 micro, 256 threads, double-buffered smem.
// flags bit0: exact-gelu epilogue.
__global__ __launch_bounds__(256) void gemm_kernel(
    const float* __restrict__ A, const float* __restrict__ B, float* __restrict__ C,
    const float* __restrict__ bias, const float* __restrict__ addend,
    int M, int N, int K, int flags)
{
    __shared__ float As[2][16][132];
    __shared__ float Bs[2][16][68];
    int tid = threadIdx.x;
    int m0 = blockIdx.y * 128, n0 = blockIdx.x * 64;

    int rowA = tid >> 2;           // 0..63
    int kA   = (tid & 3) * 4;
    const float* Arow0 = A + (size_t)(m0 + rowA)      * K + kA;
    const float* Arow1 = A + (size_t)(m0 + rowA + 64) * K + kA;
    const float* Brow  = B + (size_t)(n0 + rowA)      * K + kA;

    int ty = tid >> 4, tx = tid & 15;
    float acc[8][4];
    #pragma unroll
    for (int i = 0; i < 8; i++)
        #pragma unroll
        for (int j = 0; j < 4; j++) acc[i][j] = 0.f;

    // preload tile 0
    {
        float4 a0 = *reinterpret_cast<const float4*>(Arow0);
        float4 a1 = *reinterpret_cast<const float4*>(Arow1);
        float4 b0 = *reinterpret_cast<const float4*>(Brow);
        As[0][kA+0][rowA] = a0.x; As[0][kA+1][rowA] = a0.y; As[0][kA+2][rowA] = a0.z; As[0][kA+3][rowA] = a0.w;
        As[0][kA+0][rowA+64] = a1.x; As[0][kA+1][rowA+64] = a1.y; As[0][kA+2][rowA+64] = a1.z; As[0][kA+3][rowA+64] = a1.w;
        Bs[0][kA+0][rowA] = b0.x; Bs[0][kA+1][rowA] = b0.y; Bs[0][kA+2][rowA] = b0.z; Bs[0][kA+3][rowA] = b0.w;
    }
    __syncthreads();

    int p = 0;
    for (int kt = 0; kt < K; kt += 16) {
        float4 na0, na1, nb0;
        bool more = (kt + 16) < K;
        if (more) {
            na0 = *reinterpret_cast<const float4*>(Arow0 + kt + 16);
            na1 = *reinterpret_cast<const float4*>(Arow1 + kt + 16);
            nb0 = *reinterpret_cast<const float4*>(Brow  + kt + 16);
        }
        #pragma unroll
        for (int kk = 0; kk < 16; kk++) {
            float4 av0 = *reinterpret_cast<const float4*>(&As[p][kk][ty*8]);
            float4 av1 = *reinterpret_cast<const float4*>(&As[p][kk][ty*8+4]);
            float4 bv  = *reinterpret_cast<const float4*>(&Bs[p][kk][tx*4]);
            float aa[8] = {av0.x,av0.y,av0.z,av0.w,av1.x,av1.y,av1.z,av1.w};
            float bb[4] = {bv.x,bv.y,bv.z,bv.w};
            #pragma unroll
            for (int i = 0; i < 8; i++)
                #pragma unroll
                for (int j = 0; j < 4; j++) acc[i][j] = fmaf(aa[i], bb[j], acc[i][j]);
        }
        if (more) {
            int q = p ^ 1;
            As[q][kA+0][rowA] = na0.x; As[q][kA+1][rowA] = na0.y; As[q][kA+2][rowA] = na0.z; As[q][kA+3][rowA] = na0.w;
            As[q][kA+0][rowA+64] = na1.x; As[q][kA+1][rowA+64] = na1.y; As[q][kA+2][rowA+64] = na1.z; As[q][kA+3][rowA+64] = na1.w;
            Bs[q][kA+0][rowA] = nb0.x; Bs[q][kA+1][rowA] = nb0.y; Bs[q][kA+2][rowA] = nb0.z; Bs[q][kA+3][rowA] = nb0.w;
        }
        __syncthreads();
        p ^= 1;
    }

    float4 bb4 = make_float4(0.f,0.f,0.f,0.f);
    if (bias) bb4 = *reinterpret_cast<const float4*>(&bias[n0 + tx*4]);
    #pragma unroll
    for (int i = 0; i < 8; i++) {
        int mm = m0 + ty*8 + i;
        size_t off = (size_t)mm * N + n0 + tx*4;
        float v[4] = {acc[i][0] + bb4.x, acc[i][1] + bb4.y, acc[i][2] + bb4.z, acc[i][3] + bb4.w};
        if (addend) {
            float4 ad = *reinterpret_cast<const float4*>(&addend[off]);
            v[0] += ad.x; v[1] += ad.y; v[2] += ad.z; v[3] += ad.w;
        }
        if (flags & 1) {
            #pragma unroll
            for (int j = 0; j < 4; j++)
                v[j] = 0.5f * v[j] * (1.f + erff(v[j] * 0.70710678118654752f));
        }
        *reinterpret_cast<float4*>(&C[off]) = make_float4(v[0], v[1], v[2], v[3]);
    }
}

// ---------------- conv+silu, x_proj, dt_proj, softplus (block per (token, m)) -----------
__global__ __launch_bounds__(128) void xproj_kernel(
    const float* __restrict__ scb, const float* __restrict__ sdpb,
    const float* __restrict__ tcb, const float* __restrict__ tdpb,
    const float* __restrict__ sxpw, const float* __restrict__ txpw)
{
    int m = blockIdx.y;
    int r = blockIdx.x;
    int tid = threadIdx.x;
    int pos  = m ? ((r / NSP) & (TT-1)) : (r % NSP);
    int strd = m ? NSP : 1;
    const float* cb   = m ? tcb  : scb;
    const float* dpb  = m ? tdpb : sdpb;
    const float* xpw  = m ? txpw : sxpw;
    const float* cwT  = g_cwT[m];
    const float* dpwT = g_dpwT[m];
    int xzoff = m * 768;
    __shared__ float su[DI];
    __shared__ float sdbc[DTR + 2*DS];

    // conv4 + silu
    #pragma unroll
    for (int i = 0; i < 3; i++) {
        int d = tid + 128*i;
        float acc = cb[d];
        #pragma unroll
        for (int k = 0; k < 4; k++) {
            if (pos - 3 + k >= 0)
                acc = fmaf(cwT[k*DI + d], g_xz[(size_t)(r - (3-k)*strd) * XZW + xzoff + d], acc);
        }
        float uu = acc / (1.f + __expf(-acc));
        su[d] = uu;
        g_u[m][(size_t)r * DI + d] = uu;
    }
    __syncthreads();

    // x_proj: 4 warps x 11 outputs, lanes split K (coalesced weight reads)
    int warp = tid >> 5, lane = tid & 31;
    #pragma unroll
    for (int oi = 0; oi < 11; oi++) {
        int o = warp * 11 + oi;
        const float* wr = xpw + (size_t)o * DI;
        float acc = 0.f;
        #pragma unroll
        for (int i = 0; i < 12; i++)
            acc = fmaf(su[lane + 32*i], wr[lane + 32*i], acc);
        #pragma unroll
        for (int off = 16; off; off >>= 1)
            acc += __shfl_xor_sync(0xffffffffu, acc, off);
        if (lane == 0) sdbc[o] = acc;
    }
    __syncthreads();

    if (tid < 2*DS) g_bc[m][(size_t)r * (2*DS) + tid] = sdbc[DTR + tid];

    // dt_proj + softplus
    #pragma unroll
    for (int i = 0; i < 3; i++) {
        int d = tid + 128*i;
        float acc = dpb[d];
        #pragma unroll
        for (int rr = 0; rr < DTR; rr++)
            acc = fmaf(sdbc[rr], dpwT[rr*DI + d], acc);
        g_delta[m][(size_t)r * DI + d] = (acc > 15.f) ? acc : log1pf(__expf(acc));
    }
}

// ---------------- selective scan: warp = (seq, 2 d's); lane = (sub, state n) ------------
// all indexing token-order; rstride = 1 (spatial) or NSP (temporal)
__global__ void scan_kernel(int m, int nseq, int L, int rstride, const float* __restrict__ Dp)
{
    int gw   = (blockIdx.x * blockDim.x + threadIdx.x) >> 5;
    int lane = threadIdx.x & 31;
    int seq  = gw / (DI/2);
    int dp   = gw % (DI/2);
    if (seq >= nseq) return;
    int sub = lane >> 4, n = lane & 15;
    int d = dp * 2 + sub;

    float a  = g_A[m][d*DS + n];
    float Dd = Dp[d];
    const float* delta = g_delta[m];
    const float* u     = g_u[m];
    const float* bc    = g_bc[m];
    int ycol = m * DI + d;
    int zcol = m * 768 + 384 + d;

    int base = (rstride == 1) ? seq * L
                              : (seq / NSP) * (TT * NSP) + (seq % NSP);

    float h = 0.f;
    for (int pos = 0; pos < L; pos += 4) {
        int r[4];
        float dl[4], uu[4], Bv[4], Cv[4];
        #pragma unroll
        for (int j = 0; j < 4; j++) {
            r[j] = base + (pos + j) * rstride;
            dl[j] = __ldg(&delta[(size_t)r[j]*DI + d]);
            uu[j] = __ldg(&u[(size_t)r[j]*DI + d]);
            Bv[j] = __ldg(&bc[(size_t)r[j]*(2*DS) + n]);
            Cv[j] = __ldg(&bc[(size_t)r[j]*(2*DS) + DS + n]);
        }
        float dA[4], dBu[4];
        #pragma unroll
        for (int j = 0; j < 4; j++) {
            dA[j]  = __expf(dl[j] * a);
            dBu[j] = dl[j] * uu[j] * Bv[j];
        }
        float part[4];
        #pragma unroll
        for (int j = 0; j < 4; j++) {
            h = fmaf(h, dA[j], dBu[j]);
            part[j] = h * Cv[j];
        }
        #pragma unroll
        for (int off = 1; off <= 8; off <<= 1)
            #pragma unroll
            for (int j = 0; j < 4; j++)
                part[j] += __shfl_xor_sync(0xffffffffu, part[j], off);
        if (n == 0) {
            #pragma unroll
            for (int j = 0; j < 4; j++) {
                float z  = g_xz[(size_t)r[j]*XZW + zcol];
                float g  = z / (1.f + __expf(-z));
                g_y[(size_t)r[j] * (2*DI) + ycol] = (part[j] + uu[j] * Dd) * g;
            }
        }
    }
}

// ---------------- final tiled transpose [bt, n, c] -> [bt, c, n] ----------------
__global__ __launch_bounds__(256) void out_transpose(float* __restrict__ out)
{
    __shared__ float s[32][193];
    int bt = blockIdx.x;
    int n0 = blockIdx.y * 32;
    int tid = threadIdx.x;
    #pragma unroll
    for (int i = 0; i < 24; i++) {
        int idx = tid + 256*i;
        int nl = idx / CDIM, c = idx % CDIM;
        s[nl][c] = g_xn[((size_t)bt*NSP + n0 + nl)*CDIM + c];
    }
    __syncthreads();
    #pragma unroll
    for (int i = 0; i < 24; i++) {
        int idx = tid + 256*i;
        int c = idx >> 5, nl = idx & 31;
        out[((size_t)bt*CDIM + c)*NSP + n0 + nl] = s[nl][c];
    }
}

// ---------------- host launcher ----------------
extern "C" void kernel_launch(void* const* d_in, const int* in_sizes, int n_in,
                              void* d_out, int out_size)
{
    const float* x_in   = (const float*)d_in[0];
    const float* n1w    = (const float*)d_in[1];
    const float* n1b    = (const float*)d_in[2];
    const float* s_inw  = (const float*)d_in[3];
    const float* s_cw   = (const float*)d_in[4];
    const float* s_cb   = (const float*)d_in[5];
    const float* s_xpw  = (const float*)d_in[6];
    const float* s_dpw  = (const float*)d_in[7];
    const float* s_dpb  = (const float*)d_in[8];
    const float* s_Alog = (const float*)d_in[9];
    const float* s_D    = (const float*)d_in[10];
    const float* s_outw = (const float*)d_in[11];
    const float* t_inw  = (const float*)d_in[12];
    const float* t_cw   = (const float*)d_in[13];
    const float* t_cb   = (const float*)d_in[14];
    const float* t_xpw  = (const float*)d_in[15];
    const float* t_dpw  = (const float*)d_in[16];
    const float* t_dpb  = (const float*)d_in[17];
    const float* t_Alog = (const float*)d_in[18];
    const float* t_D    = (const float*)d_in[19];
    const float* t_outw = (const float*)d_in[20];
    const float* fw     = (const float*)d_in[21];
    const float* fb     = (const float*)d_in[22];
    const float* n2w    = (const float*)d_in[23];
    const float* n2b    = (const float*)d_in[24];
    const float* w1     = (const float*)d_in[25];
    const float* b1     = (const float*)d_in[26];
    const float* w2     = (const float*)d_in[27];
    const float* b2     = (const float*)d_in[28];
    float* out = (float*)d_out;

    float *p_xn, *p_short, *p_xz, *p_y, *p_x2, *p_h, *p_hid, *p_W12, *p_Win;
    cudaGetSymbolAddress((void**)&p_xn,   g_xn);
    cudaGetSymbolAddress((void**)&p_short,g_short);
    cudaGetSymbolAddress((void**)&p_xz,   g_xz);
    cudaGetSymbolAddress((void**)&p_y,    g_y);
    cudaGetSymbolAddress((void**)&p_x2,   g_x2);
    cudaGetSymbolAddress((void**)&p_h,    g_h);
    cudaGetSymbolAddress((void**)&p_hid,  g_hid);
    cudaGetSymbolAddress((void**)&p_W12,  g_W12);
    cudaGetSymbolAddress((void**)&p_Win,  g_Win);

    // 0. prep: A, transposed small weights, concat in_proj, folded fusion
    prep_kernel<<<1152, 256>>>(s_Alog, t_Alog, fw, s_outw, t_outw,
                               s_cw, t_cw, s_dpw, t_dpw, s_inw, t_inw);

    // 1. transpose + LN1 (keeps shortcut)
    ln1_kernel<<<dim3(16, 18), 256>>>(x_in, n1w, n1b);

    // 2. merged in_proj GEMM (N=1536)
    gemm_kernel<<<dim3(XZW/64, TOK/128), 256>>>(p_xn, p_Win, p_xz, nullptr, nullptr, TOK, XZW, CDIM, 0);

    // 3. conv+silu + x_proj + dt_proj + softplus (both mambas, one launch)
    xproj_kernel<<<dim3(TOK, 2), 128>>>(s_cb, s_dpb, t_cb, t_dpb, s_xpw, t_xpw);

    // 4. selective scans (token-order, gated outputs into merged y buffer)
    scan_kernel<<<(16   * (DI/2)) / 4, 128>>>(0, 16,      NSP, 1,   s_D);
    scan_kernel<<<(1152 * (DI/2)) / 4, 128>>>(1, BQ*NSP,  TT,  NSP, t_D);

    // 5. merged out_proj + fusion + residual: x2 = short + fb + y @ W12^T  (K=768)
    gemm_kernel<<<dim3(CDIM/64, TOK/128), 256>>>(p_y, p_W12, p_x2, fb, p_short, TOK, CDIM, 2*DI, 0);

    // 6. LN2 + MLP + residual
    ln2_kernel<<<TOK/4, 128>>>(p_x2, p_h, n2w, n2b);
    gemm_kernel<<<dim3(MLPH/64, TOK/128), 256>>>(p_h,   w1, p_hid, b1, nullptr, TOK, MLPH, CDIM, 1);
    gemm_kernel<<<dim3(CDIM/64, TOK/128), 256>>>(p_hid, w2, p_xn,  b2, p_x2,    TOK, CDIM, MLPH, 0);

    // 7. output tiled transpose [bt,n,c] -> [b,t,c,h,w]
    out_transpose<<<dim3(16, 18), 256>>>(out);
}